// round 14
// baseline (speedup 1.0000x reference)
#include <cuda_runtime.h>
#include <cuda_bf16.h>
#include <cuda_fp16.h>
#include <cstdint>

typedef __nv_bfloat16 bf16;

#define B_  2
#define S_  1024
#define D_  1024
#define H_  16
#define DH_ 64

static const long long SZ_TOK = 2097152LL;
static const long long SZ_W   = 1048576LL;
static const long long SZ_ATT = 33554432LL;

// ---- half pool offsets (elements) ----
#define HXH   (0LL  * SZ_TOK)
#define HXL   (1LL  * SZ_TOK)
#define HX2   (2LL  * SZ_TOK)
#define HVX   (3LL  * SZ_TOK)
#define HQH   (4LL  * SZ_TOK)
#define HQL   (5LL  * SZ_TOK)
#define HQ2   (6LL  * SZ_TOK)
#define HKH   (7LL  * SZ_TOK)
#define HKL   (8LL  * SZ_TOK)
#define HVT   (9LL  * SZ_TOK)
#define HVQ   (10LL * SZ_TOK)
#define HVK   (11LL * SZ_TOK)
#define HVKK  (12LL * SZ_TOK)
#define HW0   (13LL * SZ_TOK)
#define WQMH  (HW0 + 0LL  * SZ_W)
#define WQML  (HW0 + 1LL  * SZ_W)
#define WQV   (HW0 + 2LL  * SZ_W)
#define WQP   (HW0 + 3LL  * SZ_W)
#define WKMH  (HW0 + 4LL  * SZ_W)
#define WKML  (HW0 + 5LL  * SZ_W)
#define WKV   (HW0 + 6LL  * SZ_W)
#define WKP   (HW0 + 7LL  * SZ_W)
#define WVMH  (HW0 + 8LL  * SZ_W)
#define WVML  (HW0 + 9LL  * SZ_W)
#define WVV   (HW0 + 10LL * SZ_W)
#define WVP   (HW0 + 11LL * SZ_W)
#define HPH   (HW0 + 12LL * SZ_W)
#define H_TOTAL (HPH + SZ_ATT)

// ---- bf16 pool offsets ----
#define BP2   (0LL)
#define BG    (1LL * SZ_ATT)
#define BVVT  (2LL * SZ_ATT)
#define BVVVT (2LL * SZ_ATT + SZ_TOK)
#define B_TOTAL (2LL * SZ_ATT + 2LL * SZ_TOK)

__device__ half  g_h[H_TOTAL];
__device__ bf16  g_b[B_TOTAL];
__device__ float g_kf[SZ_TOK];
__device__ float g_vf[SZ_TOK];

// ---------------------------------------------------------------------------
__device__ __forceinline__ uint32_t smem_to_u32(const void* p) {
    uint32_t a;
    asm("{ .reg .u64 t; cvta.to.shared.u64 t, %1; cvt.u32.u64 %0, t; }" : "=r"(a) : "l"(p));
    return a;
}
__device__ __forceinline__ void cp16(uint32_t s, const void* g) {
    asm volatile("cp.async.cg.shared.global [%0], [%1], 16;" :: "r"(s), "l"(g) : "memory");
}
#define CP_COMMIT() asm volatile("cp.async.commit_group;" ::: "memory")
#define CP_WAIT(n)  asm volatile("cp.async.wait_group %0;" :: "n"(n) : "memory")
#define SW128(x) ((x) ^ (((x) >> 3) & 0x70))
#define SW64(x)  ((x) ^ (((x) >> 3) & 0x30))

__device__ __forceinline__ void ldsm4(uint32_t* r, uint32_t addr) {
    asm volatile("ldmatrix.sync.aligned.m8n8.x4.shared.b16 {%0,%1,%2,%3}, [%4];"
        : "=r"(r[0]), "=r"(r[1]), "=r"(r[2]), "=r"(r[3]) : "r"(addr));
}
__device__ __forceinline__ void mma_h(float* c, const uint32_t* a, const uint32_t* b) {
    asm volatile(
        "mma.sync.aligned.m16n8k16.row.col.f32.f16.f16.f32 "
        "{%0,%1,%2,%3}, {%4,%5,%6,%7}, {%8,%9}, {%0,%1,%2,%3};"
        : "+f"(c[0]), "+f"(c[1]), "+f"(c[2]), "+f"(c[3])
        : "r"(a[0]), "r"(a[1]), "r"(a[2]), "r"(a[3]), "r"(b[0]), "r"(b[1]));
}
__device__ __forceinline__ void mma_b(float* c, const uint32_t* a, const uint32_t* b) {
    asm volatile(
        "mma.sync.aligned.m16n8k16.row.col.f32.bf16.bf16.f32 "
        "{%0,%1,%2,%3}, {%4,%5,%6,%7}, {%8,%9}, {%0,%1,%2,%3};"
        : "+f"(c[0]), "+f"(c[1]), "+f"(c[2]), "+f"(c[3])
        : "r"(a[0]), "r"(a[1]), "r"(a[2]), "r"(a[3]), "r"(b[0]), "r"(b[1]));
}
__device__ __forceinline__ void hsplit(float a, half* h, half* l) {
    half hh = __float2half(a);
    *h = hh; *l = __float2half(a - __half2float(hh));
}
__device__ __forceinline__ void st1(half* p, float v) { *p = __float2half(v); }
__device__ __forceinline__ void st1(bf16* p, float v) { *p = __float2bfloat16(v); }
__device__ __forceinline__ void stsp(half* h, half* l, float v) { hsplit(v, h, l); }
__device__ __forceinline__ void stsp(bf16* h, bf16* l, float v) {
    bf16 hh = __float2bfloat16(v);
    *h = hh; *l = __float2bfloat16(v - __bfloat162float(hh));
}
__device__ __forceinline__ uint32_t pkh(float a, float b) {
    return (uint32_t)__half_as_ushort(__float2half(a)) |
           ((uint32_t)__half_as_ushort(__float2half(b)) << 16);
}
__device__ __forceinline__ uint32_t pkb(float a, float b) {
    return (uint32_t)__bfloat16_as_ushort(__float2bfloat16(a)) |
           ((uint32_t)__bfloat16_as_ushort(__float2bfloat16(b)) << 16);
}

// ---------------------------------------------------------------------------
__global__ void conv_all_k(const float* __restrict__ x, const float* __restrict__ vx,
                           const float* __restrict__ wqm, const float* __restrict__ wqv,
                           const float* __restrict__ wkm, const float* __restrict__ wkv,
                           const float* __restrict__ wvm, const float* __restrict__ wvv,
                           half* __restrict__ hp) {
    const int i = blockIdx.x * 256 + threadIdx.x;
    if (i < (int)SZ_TOK) {
        float a = x[i];
        hsplit(a, hp + HXH + i, hp + HXL + i);
        hp[HX2 + i] = __float2half(a * a);
        hp[HVX + i] = __float2half(vx[i]);
    }
    if (i < (int)SZ_W) {
        float m, v;
        m = wqm[i]; v = wqv[i];
        hsplit(m, hp + WQMH + i, hp + WQML + i);
        hp[WQV + i] = __float2half(v);
        hp[WQP + i] = __float2half(fmaf(m, m, v));
        m = wkm[i]; v = wkv[i];
        hsplit(m, hp + WKMH + i, hp + WKML + i);
        hp[WKV + i] = __float2half(v);
        hp[WKP + i] = __float2half(fmaf(m, m, v));
        m = wvm[i]; v = wvv[i];
        hsplit(m, hp + WVMH + i, hp + WVML + i);
        hp[WVV + i] = __float2half(v);
        hp[WVP + i] = __float2half(fmaf(m, m, v));
    }
}

// ---------------------------------------------------------------------------
// GEMM body: 64B SW64 rows, 3-stage pipeline, 1 sync/chunk (unchanged)
// ---------------------------------------------------------------------------
template<int BN, int MODE, bool F16, typename OT>
__device__ __forceinline__
void gemm_body(const uint16_t* __restrict__ A0, const uint16_t* __restrict__ A1,
               const uint16_t* __restrict__ B0, const uint16_t* __restrict__ B1,
               int K, int lda, int ldb, int ldc,
               long long sbA, long long shA, long long sbB, long long shB,
               long long sbC, long long shC, int bz,
               float alpha,
               float* __restrict__ cf, const float* __restrict__ addp,
               OT* __restrict__ ch, OT* __restrict__ cl, OT* __restrict__ cs,
               const float* __restrict__ auxf, OT* __restrict__ ds, int auxmode,
               int transC)
{
    constexpr int BM = 128, BK = 32;
    constexpr int NMATB = (MODE == 2) ? 1 : 2;
    constexpr int WARPS_N = (BN == 128) ? 4 : 2;
    constexpr int WARPS_M = 8 / WARPS_N;
    constexpr int WM = BM / WARPS_M, WN = BN / WARPS_N;
    constexpr int MT = WM / 16, NT = WN / 8;
    constexpr int ATILE = BM * 64;
    constexpr int BTILE = BN * 64;
    constexpr int BUFB  = 2 * ATILE + NMATB * BTILE;

    extern __shared__ char smem[];
    const uint32_t s32 = smem_to_u32(smem);
    const int tid = threadIdx.x;
    const int wid = tid >> 5, lane = tid & 31;
    const int wm = wid / WARPS_N, wn = wid % WARPS_N;

    const int bb = bz >> 4, hh = bz & 15;
    const long long offA = (long long)bb * sbA + (long long)hh * shA;
    const long long offB = (long long)bb * sbB + (long long)hh * shB;
    const long long offC = (long long)bb * sbC + (long long)hh * shC;
    const int m0 = blockIdx.y * BM;
    const int n0 = blockIdx.x * BN;

    auto loadbuf = [&](int kc, int buf) {
        const int k0 = kc * BK;
        const uint32_t b32 = s32 + buf * BUFB;
#pragma unroll
        for (int i = 0; i < BM * 4 / 256; i++) {
            const int c = tid + i * 256;
            const int row = c >> 2, seg = c & 3;
            const long long go = offA + (long long)(m0 + row) * lda + k0 + seg * 8;
            const uint32_t so = SW64((uint32_t)(row * 64 + seg * 16));
            cp16(b32 + so, A0 + go);
            cp16(b32 + ATILE + so, A1 + go);
        }
#pragma unroll
        for (int i = 0; i < BN * 4 / 256; i++) {
            const int c = tid + i * 256;
            const int row = c >> 2, seg = c & 3;
            const long long go = offB + (long long)(n0 + row) * ldb + k0 + seg * 8;
            const uint32_t so = SW64((uint32_t)(row * 64 + seg * 16));
            cp16(b32 + 2 * ATILE + so, B0 + go);
            if (NMATB == 2) cp16(b32 + 2 * ATILE + BTILE + so, B1 + go);
        }
        CP_COMMIT();
    };

    float acc[MT][NT][4];
#pragma unroll
    for (int i = 0; i < MT; i++)
#pragma unroll
        for (int j = 0; j < NT; j++)
#pragma unroll
            for (int r = 0; r < 4; r++) acc[i][j][r] = 0.f;

    const int NKC = K / BK;
    loadbuf(0, 0);
    if (NKC > 1) loadbuf(1, 1);

    for (int kc = 0; kc < NKC; kc++) {
        const int buf = kc % 3;
        if (kc < NKC - 1) { CP_WAIT(1); } else { CP_WAIT(0); }
        __syncthreads();
        if (kc + 2 < NKC) loadbuf(kc + 2, (kc + 2) % 3);

        const uint32_t b32 = s32 + buf * BUFB;
#pragma unroll
        for (int kh = 0; kh < 2; kh++) {
            const int kcol = kh * 16 + (lane >> 4) * 8;
            uint32_t afr[2][MT][4];
            uint32_t bfr[NMATB][NT][2];
#pragma unroll
            for (int mat = 0; mat < 2; mat++)
#pragma unroll
                for (int mt = 0; mt < MT; mt++) {
                    const int row = wm * WM + mt * 16 + (lane & 15);
                    ldsm4(afr[mat][mt], b32 + mat * ATILE + SW64((uint32_t)(row * 64 + kcol * 2)));
                }
#pragma unroll
            for (int mat = 0; mat < NMATB; mat++)
#pragma unroll
                for (int nt2 = 0; nt2 < NT / 2; nt2++) {
                    const int row = wn * WN + nt2 * 16 + (lane & 15);
                    uint32_t r[4];
                    ldsm4(r, b32 + 2 * ATILE + mat * BTILE + SW64((uint32_t)(row * 64 + kcol * 2)));
                    bfr[mat][2 * nt2][0]     = r[0]; bfr[mat][2 * nt2][1]     = r[2];
                    bfr[mat][2 * nt2 + 1][0] = r[1]; bfr[mat][2 * nt2 + 1][1] = r[3];
                }

#define DO_MMA(AM, BM_) \
            for (int mt = 0; mt < MT; mt++) \
                for (int nt = 0; nt < NT; nt++) { \
                    if (F16) mma_h(acc[mt][nt], afr[AM][mt], bfr[BM_][nt]); \
                    else     mma_b(acc[mt][nt], afr[AM][mt], bfr[BM_][nt]); \
                }
            DO_MMA(0, 0)
            if (MODE == 0) { DO_MMA(1, 0) DO_MMA(0, 1) }
            else if (MODE == 1) { DO_MMA(1, 1) }
            else { DO_MMA(1, 0) }
#undef DO_MMA
        }
    }

#pragma unroll
    for (int mt = 0; mt < MT; mt++) {
#pragma unroll
        for (int nt = 0; nt < NT; nt++) {
#pragma unroll
            for (int rp = 0; rp < 2; rp++) {
                const int m = m0 + wm * WM + mt * 16 + (lane >> 2) + rp * 8;
                const int nbase = n0 + wn * WN + nt * 8 + (lane & 3) * 2;
#pragma unroll
                for (int cc = 0; cc < 2; cc++) {
                    const int n = nbase + cc;
                    float val = alpha * acc[mt][nt][rp * 2 + cc];
                    const long long idx = offC + (long long)m * ldc + n;
                    if (addp) val += addp[idx];
                    if (cf) cf[idx] = val;
                    const long long bidx = transC
                        ? ((long long)(m >> 10) * ((long long)D_ * S_) + (long long)n * S_ + (m & (S_ - 1)))
                        : idx;
                    if (ch) stsp(ch + bidx, cl + bidx, val);
                    if (cs) st1(cs + bidx, val);
                    if (auxmode) {
                        const float t = (auxmode == 1) ? val * val
                                                       : fmaf(auxf[idx], auxf[idx], val);
                        st1(ds + bidx, t);
                    }
                }
            }
        }
    }
}

// ---------------------------------------------------------------------------
__global__ __launch_bounds__(256, 2)
void proj_a_k(half* __restrict__ hp, float* __restrict__ kf, float* __restrict__ vf) {
    const uint16_t* u = (const uint16_t*)hp;
    switch (blockIdx.z) {
    case 0:
        gemm_body<128, 0, true, half>(u + HXH, u + HXL, u + WQMH, u + WQML,
            D_, D_, D_, D_, 0, 0, 0, 0, 0, 0, 0, 1.f,
            nullptr, nullptr, hp + HQH, hp + HQL, nullptr, nullptr, hp + HQ2, 1, 0);
        break;
    case 1:
        gemm_body<128, 0, true, half>(u + HXH, u + HXL, u + WKMH, u + WKML,
            D_, D_, D_, D_, 0, 0, 0, 0, 0, 0, 0, 1.f,
            kf, nullptr, hp + HKH, hp + HKL, nullptr, nullptr, nullptr, 0, 0);
        break;
    case 2:
        gemm_body<128, 0, true, half>(u + HXH, u + HXL, u + WVMH, u + WVML,
            D_, D_, D_, D_, 0, 0, 0, 0, 0, 0, 0, 1.f,
            vf, nullptr, nullptr, nullptr, hp + HVT, nullptr, nullptr, 0, 1);
        break;
    default:
        gemm_body<128, 1, true, half>(u + HVX, u + HX2, u + WQP, u + WQV,
            D_, D_, D_, D_, 0, 0, 0, 0, 0, 0, 0, 1.f,
            nullptr, nullptr, nullptr, nullptr, hp + HVQ, nullptr, nullptr, 0, 0);
        break;
    }
}

__global__ __launch_bounds__(256, 2)
void proj_b_k(half* __restrict__ hp, bf16* __restrict__ bp,
              const float* __restrict__ kf, const float* __restrict__ vf) {
    const uint16_t* u = (const uint16_t*)hp;
    if (blockIdx.z == 0) {
        gemm_body<128, 1, true, half>(u + HVX, u + HX2, u + WKP, u + WKV,
            D_, D_, D_, D_, 0, 0, 0, 0, 0, 0, 0, 1.f,
            nullptr, nullptr, nullptr, nullptr, hp + HVK, kf, hp + HVKK, 2, 0);
    } else {
        gemm_body<128, 1, true, bf16>(u + HVX, u + HX2, u + WVP, u + WVV,
            D_, D_, D_, D_, 0, 0, 0, 0, 0, 0, 0, 1.f,
            nullptr, nullptr, nullptr, nullptr, bp + BVVT, vf, bp + BVVVT, 2, 1);
    }
}

// ---------------------------------------------------------------------------
// av body (unchanged from R13). MODE 3: A0B0 only | MODE 1: A0B0+A1B1
// ---------------------------------------------------------------------------
template<int MODE, bool F16>
__device__ __forceinline__
void av_body(const uint16_t* __restrict__ A0, const uint16_t* __restrict__ A1,
             const uint16_t* __restrict__ B0f, const uint16_t* __restrict__ B1f,
             int bh, const float* __restrict__ addp, float* __restrict__ cf)
{
    constexpr int SK = 40;
    constexpr int BT = 64 * SK * 2;
    constexpr int NMATB = (MODE == 1) ? 2 : 1;
    constexpr int NMATA = (MODE == 3) ? 1 : 2;
    constexpr int BUFB = NMATB * BT;

    extern __shared__ char smem[];
    const uint32_t s32 = smem_to_u32(smem);
    const int tid = threadIdx.x, wid = tid >> 5, lane = tid & 31;
    const int wm = wid >> 1, wn = wid & 1;
    const int bb = bh >> 4, hh = bh & 15;
    const int m0 = blockIdx.y * 128;

    const long long attBase = (long long)bh << 20;
    const long long offB = (long long)bb * ((long long)D_ * S_) + (long long)hh * (DH_ * S_);
    const long long offC = (long long)bb * ((long long)S_ * D_) + (long long)hh * DH_;

    const int brow = tid >> 2, bseg = tid & 3;
    auto loadB = [&](int kc, int buf) {
        const int k0 = kc * 32;
        const uint32_t b32 = s32 + buf * BUFB;
        const long long go = offB + (long long)brow * S_ + k0 + bseg * 8;
        const uint32_t so = (uint32_t)(brow * SK + bseg * 8) * 2;
        cp16(b32 + so, B0f + go);
        if (NMATB == 2) cp16(b32 + BT + so, B1f + go);
        CP_COMMIT();
    };

    float acc[2][4][4];
#pragma unroll
    for (int mt = 0; mt < 2; mt++)
#pragma unroll
        for (int nt = 0; nt < 4; nt++)
#pragma unroll
            for (int r = 0; r < 4; r++) acc[mt][nt][r] = 0.f;

    const int mtile0 = (m0 >> 4) + wm * 2;

    loadB(0, 0);
    loadB(1, 1);
    for (int kc = 0; kc < 32; kc++) {
        const int buf = kc % 3;
        uint32_t af[NMATA][2][2][4];
#pragma unroll
        for (int mt = 0; mt < 2; mt++)
#pragma unroll
            for (int ks = 0; ks < 2; ks++) {
                const long long base = attBase + (long long)(mtile0 + mt) * 16384
                                     + (long long)(kc * 4 + ks * 2) * 128 + lane * 4;
                uint2 v0 = *(const uint2*)(A0 + base);
                uint2 v1 = *(const uint2*)(A0 + base + 128);
                af[0][mt][ks][0] = v0.x; af[0][mt][ks][1] = v0.y;
                af[0][mt][ks][2] = v1.x; af[0][mt][ks][3] = v1.y;
                if (NMATA == 2) {
                    uint2 w0 = *(const uint2*)(A1 + base);
                    uint2 w1 = *(const uint2*)(A1 + base + 128);
                    af[NMATA - 1][mt][ks][0] = w0.x; af[NMATA - 1][mt][ks][1] = w0.y;
                    af[NMATA - 1][mt][ks][2] = w1.x; af[NMATA - 1][mt][ks][3] = w1.y;
                }
            }

        if (kc < 30) { CP_WAIT(1); } else { CP_WAIT(0); }
        __syncthreads();
        if (kc + 2 < 32) loadB(kc + 2, (kc + 2) % 3);
        const uint32_t b32 = s32 + buf * BUFB;

#pragma unroll
        for (int ks = 0; ks < 2; ks++) {
            const int kcol = ks * 16 + (lane >> 4) * 8;
            uint32_t bfr[NMATB][4][2];
#pragma unroll
            for (int mat = 0; mat < NMATB; mat++)
#pragma unroll
                for (int nt2 = 0; nt2 < 2; nt2++) {
                    const int row = wn * 32 + nt2 * 16 + (lane & 15);
                    uint32_t r4[4];
                    ldsm4(r4, b32 + mat * BT + (uint32_t)(row * SK + kcol) * 2);
                    bfr[mat][2 * nt2][0]     = r4[0]; bfr[mat][2 * nt2][1]     = r4[2];
                    bfr[mat][2 * nt2 + 1][0] = r4[1]; bfr[mat][2 * nt2 + 1][1] = r4[3];
                }
#pragma unroll
            for (int mt = 0; mt < 2; mt++)
#pragma unroll
                for (int nt = 0; nt < 4; nt++) {
                    if (F16) {
                        mma_h(acc[mt][nt], af[0][mt][ks], bfr[0][nt]);
                        if (MODE != 3)
                            mma_h(acc[mt][nt], af[NMATA - 1][mt][ks], bfr[NMATB - 1][nt]);
                    } else {
                        mma_b(acc[mt][nt], af[0][mt][ks], bfr[0][nt]);
                        if (MODE != 3)
                            mma_b(acc[mt][nt], af[NMATA - 1][mt][ks], bfr[NMATB - 1][nt]);
                    }
                }
        }
    }

#pragma unroll
    for (int mt = 0; mt < 2; mt++)
#pragma unroll
        for (int nt = 0; nt < 4; nt++)
#pragma unroll
            for (int rp = 0; rp < 2; rp++) {
                const int m = m0 + wm * 32 + mt * 16 + (lane >> 2) + rp * 8;
                const int nbase = wn * 32 + nt * 8 + (lane & 3) * 2;
#pragma unroll
                for (int cc = 0; cc < 2; cc++) {
                    const int n = nbase + cc;
                    float val = acc[mt][nt][rp * 2 + cc];
                    const long long idx = offC + (long long)m * D_ + n;
                    if (addp) val += addp[idx];
                    cf[idx] = val;
                }
            }
}

__global__ __launch_bounds__(256, 2)
void av_k(half* __restrict__ hp, bf16* __restrict__ bp,
          const float* __restrict__ x, float* __restrict__ out) {
    const uint16_t* u = (const uint16_t*)hp;
    const int op = blockIdx.z >> 5;
    const int bh = blockIdx.z & 31;
    if (op == 0) {
        av_body<3, true>(u + HPH, nullptr, u + HVT, nullptr, bh, x, out);
    } else {
        av_body<1, false>((const uint16_t*)(bp + BG), (const uint16_t*)(bp + BP2),
                          (const uint16_t*)(bp + BVVVT), (const uint16_t*)(bp + BVVT),
                          bh, nullptr, out + SZ_TOK);
    }
}

// ---------------------------------------------------------------------------
// R14 scores_k: per-chunk MMA work split into 5 independent accumulator
// chains (3 mu terms + 2 VS terms), reduced at chunk end -> serial depth 4.
// ---------------------------------------------------------------------------
__global__ __launch_bounds__(256, 2)
void scores_k(const uint16_t* __restrict__ qh, const uint16_t* __restrict__ ql,
              const uint16_t* __restrict__ vq, const uint16_t* __restrict__ q2,
              const uint16_t* __restrict__ kh, const uint16_t* __restrict__ kl,
              const uint16_t* __restrict__ vkk, const uint16_t* __restrict__ vk,
              half* __restrict__ ph,
              bf16* __restrict__ p2, bf16* __restrict__ g)
{
    constexpr int QT = 16 * 128;
    constexpr int QB = 4 * QT;
    constexpr int KT = 64 * 128;
    constexpr int KBUF = 4 * KT;
    constexpr int RB = QB + 3 * KBUF;

    extern __shared__ char smem[];
    const uint32_t s32 = smem_to_u32(smem);
    const int tid = threadIdx.x, wid = tid >> 5, lane = tid & 31;
    const int bh = blockIdx.y, bb = bh >> 4, hh = bh & 15;
    const int m0 = blockIdx.x * 16;
    const long long tokOff = (long long)bb * S_ * D_ + (long long)hh * DH_;
    const long long fragBase = ((long long)bh << 20) + (long long)blockIdx.x * 16384;
    const float vscale = 1.0f / 1024.0f;

#pragma unroll
    for (int i = 0; i < 2; i++) {
        const int c = tid + i * 256;
        const int arr = c >> 7, r = (c >> 3) & 15, seg = c & 7;
        const uint16_t* src = (arr == 0) ? qh : (arr == 1) ? ql : (arr == 2) ? vq : q2;
        cp16(s32 + arr * QT + SW128((uint32_t)(r * 128 + seg * 16)),
             src + tokOff + (long long)(m0 + r) * D_ + seg * 8);
    }
    CP_COMMIT();

    auto loadK = [&](int c0, int buf) {
        const uint32_t kb = s32 + QB + buf * KBUF;
#pragma unroll
        for (int i = 0; i < 8; i++) {
            const int c = tid + i * 256;
            const int arr = c >> 9, rr = (c >> 3) & 63, seg = c & 7;
            const uint16_t* src = (arr == 0) ? kh : (arr == 1) ? kl : (arr == 2) ? vkk : vk;
            cp16(kb + arr * KT + SW128((uint32_t)(rr * 128 + seg * 16)),
                 src + tokOff + (long long)(c0 * 64 + rr) * D_ + seg * 8);
        }
        CP_COMMIT();
    };

    float acc[16][4];
#pragma unroll
    for (int c = 0; c < 16; c++)
#pragma unroll
        for (int r = 0; r < 4; r++) acc[c][r] = 0.f;

    const int brow = wid * 8 + (lane & 7);
    const int bgrp = (lane >> 3) * 8;

    loadK(0, 0);
    loadK(1, 1);
#pragma unroll
    for (int c0 = 0; c0 < 16; c0++) {
        const int buf = c0 % 3;
        if (c0 < 14) { CP_WAIT(1); } else { CP_WAIT(0); }
        __syncthreads();
        if (c0 + 2 < 16) loadK(c0 + 2, (c0 + 2) % 3);
        const uint32_t kb = s32 + QB + buf * KBUF;

        // 5 independent accumulator chains (serial depth 4 each)
        float chA[4] = {0.f, 0.f, 0.f, 0.f};
        float chB[4] = {0.f, 0.f, 0.f, 0.f};
        float chC[4] = {0.f, 0.f, 0.f, 0.f};
        float chV0[4] = {0.f, 0.f, 0.f, 0.f};
        float chV1[4] = {0.f, 0.f, 0.f, 0.f};
#pragma unroll
        for (int kp = 0; kp < 2; kp++) {
            uint32_t bfp[4][4];
#pragma unroll
            for (int m = 0; m < 4; m++)
                ldsm4(bfp[m], kb + m * KT + SW128((uint32_t)(brow * 128 + (kp * 32 + bgrp) * 2)));
#pragma unroll
            for (int kk = 0; kk < 2; kk++) {
                const int ks = kp * 2 + kk;
                const int kcolA = ks * 16 + (lane >> 4) * 8;
                uint32_t af[4][4];
#pragma unroll
                for (int m = 0; m < 4; m++)
                    ldsm4(af[m], s32 + m * QT + SW128((uint32_t)((lane & 15) * 128 + kcolA * 2)));
                const uint32_t* b0 = &bfp[0][kk * 2];
                const uint32_t* b1 = &bfp[1][kk * 2];
                const uint32_t* b2 = &bfp[2][kk * 2];
                const uint32_t* b3 = &bfp[3][kk * 2];
                mma_h(chA,  af[0], b0);   // qh.kh
                mma_h(chB,  af[1], b0);   // ql.kh
                mma_h(chC,  af[0], b1);   // qh.kl
                mma_h(chV0, af[2], b2);   // vq.vkk
                mma_h(chV1, af[3], b3);   // q2.vk
            }
        }
        // reduce chains
#pragma unroll
        for (int r = 0; r < 4; r++)
            acc[c0][r] = chA[r] + chB[r] + chC[r];
        {
            const long long fidx = fragBase + (long long)(c0 * 8 + wid) * 128 + lane * 4;
            uint2 v;
            v.x = pkb((chV0[0] + chV1[0]) * vscale, (chV0[1] + chV1[1]) * vscale);
            v.y = pkb((chV0[2] + chV1[2]) * vscale, (chV0[3] + chV1[3]) * vscale);
            *(uint2*)(g + fidx) = v;
        }
    }

    float* red = (float*)(smem + RB);
    const int r0 = lane >> 2;
    const float sscale = 1.0f / 32.0f;
    float mx[2] = {-1e30f, -1e30f};
#pragma unroll
    for (int c = 0; c < 16; c++)
#pragma unroll
        for (int rp = 0; rp < 2; rp++)
            mx[rp] = fmaxf(mx[rp], fmaxf(acc[c][rp * 2], acc[c][rp * 2 + 1]));
    mx[0] *= sscale; mx[1] *= sscale;
#pragma unroll
    for (int d = 1; d <= 2; d <<= 1) {
        mx[0] = fmaxf(mx[0], __shfl_xor_sync(0xffffffff, mx[0], d));
        mx[1] = fmaxf(mx[1], __shfl_xor_sync(0xffffffff, mx[1], d));
    }
    __syncthreads();
    if ((lane & 3) == 0) {
        red[r0 * 8 + wid] = mx[0];
        red[(r0 + 8) * 8 + wid] = mx[1];
    }
    __syncthreads();
    float rmx[2];
#pragma unroll
    for (int rp = 0; rp < 2; rp++) {
        float v = -1e30f;
#pragma unroll
        for (int w = 0; w < 8; w++) v = fmaxf(v, red[(r0 + rp * 8) * 8 + w]);
        rmx[rp] = v;
    }
    __syncthreads();
    float sm[2] = {0.f, 0.f};
#pragma unroll
    for (int c = 0; c < 16; c++)
#pragma unroll
        for (int rp = 0; rp < 2; rp++)
#pragma unroll
            for (int cc = 0; cc < 2; cc++) {
                float e = __expf(acc[c][rp * 2 + cc] * sscale - rmx[rp]);
                acc[c][rp * 2 + cc] = e;
                sm[rp] += e;
            }
#pragma unroll
    for (int d = 1; d <= 2; d <<= 1) {
        sm[0] += __shfl_xor_sync(0xffffffff, sm[0], d);
        sm[1] += __shfl_xor_sync(0xffffffff, sm[1], d);
    }
    if ((lane & 3) == 0) {
        red[r0 * 8 + wid] = sm[0];
        red[(r0 + 8) * 8 + wid] = sm[1];
    }
    __syncthreads();
    float inv[2];
#pragma unroll
    for (int rp = 0; rp < 2; rp++) {
        float v = 0.f;
#pragma unroll
        for (int w = 0; w < 8; w++) v += red[(r0 + rp * 8) * 8 + w];
        inv[rp] = 1.0f / v;
    }

#pragma unroll
    for (int c = 0; c < 16; c++) {
        const long long fidx = fragBase + (long long)(c * 8 + wid) * 128 + lane * 4;
        const float p0 = acc[c][0] * inv[0];
        const float p1 = acc[c][1] * inv[0];
        const float p2v = acc[c][2] * inv[1];
        const float p3 = acc[c][3] * inv[1];
        uint2 vph;
        vph.x = pkh(p0, p1);
        vph.y = pkh(p2v, p3);
        *(uint2*)(ph + fidx) = vph;
        uint2 vp2;
        vp2.x = pkb(p0 * p0, p1 * p1);
        vp2.y = pkb(p2v * p2v, p3 * p3);
        *(uint2*)(p2 + fidx) = vp2;
        const uint2 vsp = *(const uint2*)(g + fidx);
        const float vs0 = __bfloat162float(__ushort_as_bfloat16((unsigned short)(vsp.x & 0xffff)));
        const float vs1 = __bfloat162float(__ushort_as_bfloat16((unsigned short)(vsp.x >> 16)));
        const float vs2 = __bfloat162float(__ushort_as_bfloat16((unsigned short)(vsp.y & 0xffff)));
        const float vs3 = __bfloat162float(__ushort_as_bfloat16((unsigned short)(vsp.y >> 16)));
        const float pm0 = p0 * (1.0f - p0), pm1 = p1 * (1.0f - p1);
        const float pm2 = p2v * (1.0f - p2v), pm3 = p3 * (1.0f - p3);
        uint2 vg;
        vg.x = pkb(pm0 * pm0 * vs0, pm1 * pm1 * vs1);
        vg.y = pkb(pm2 * pm2 * vs2, pm3 * pm3 * vs3);
        *(uint2*)(g + fidx) = vg;
    }
}

// ---------------------------------------------------------------------------
extern "C" void kernel_launch(void* const* d_in, const int* in_sizes, int n_in,
                              void* d_out, int out_size)
{
    (void)in_sizes; (void)n_in; (void)out_size;
    const float* x      = (const float*)d_in[0];
    const float* var_x  = (const float*)d_in[1];
    const float* wq_mu  = (const float*)d_in[2];
    const float* wq_var = (const float*)d_in[3];
    const float* wk_mu  = (const float*)d_in[4];
    const float* wk_var = (const float*)d_in[5];
    const float* wv_mu  = (const float*)d_in[6];
    const float* wv_var = (const float*)d_in[7];
    float* out = (float*)d_out;

    half* hp = nullptr;  cudaGetSymbolAddress((void**)&hp, g_h);
    bf16* bp = nullptr;  cudaGetSymbolAddress((void**)&bp, g_b);
    float* kf = nullptr; cudaGetSymbolAddress((void**)&kf, g_kf);
    float* vf = nullptr; cudaGetSymbolAddress((void**)&vf, g_vf);

    const int SM128 = 3 * 32768;
    const int SMAV  = 3 * 10240;
    const int SMSC  = 8192 + 3 * 32768 + 512;
    cudaFuncSetAttribute(proj_a_k, cudaFuncAttributeMaxDynamicSharedMemorySize, SM128);
    cudaFuncSetAttribute(proj_b_k, cudaFuncAttributeMaxDynamicSharedMemorySize, SM128);
    cudaFuncSetAttribute(av_k,     cudaFuncAttributeMaxDynamicSharedMemorySize, SMAV);
    cudaFuncSetAttribute(scores_k, cudaFuncAttributeMaxDynamicSharedMemorySize, SMSC);

    conv_all_k<<<(int)(SZ_TOK / 256), 256>>>(x, var_x, wq_mu, wq_var, wk_mu, wk_var,
                                             wv_mu, wv_var, hp);

    proj_a_k<<<dim3(8, 16, 4), 256, SM128>>>(hp, kf, vf);
    proj_b_k<<<dim3(8, 16, 2), 256, SM128>>>(hp, bp, kf, vf);

    const uint16_t* u = (const uint16_t*)hp;
    scores_k<<<dim3(64, 32), 256, SMSC>>>(
        u + HQH, u + HQL, u + HVQ, u + HQ2,
        u + HKH, u + HKL, u + HVKK, u + HVK,
        hp + HPH, bp + BP2, bp + BG);

    av_k<<<dim3(1, 8, 64), 256, SMAV>>>(hp, bp, x, out);
}

// round 15
// speedup vs baseline: 1.0259x; 1.0259x over previous
#include <cuda_runtime.h>
#include <cuda_bf16.h>
#include <cuda_fp16.h>
#include <cstdint>

typedef __nv_bfloat16 bf16;

#define B_  2
#define S_  1024
#define D_  1024
#define H_  16
#define DH_ 64

static const long long SZ_TOK = 2097152LL;
static const long long SZ_W   = 1048576LL;
static const long long SZ_ATT = 33554432LL;

// ---- half pool offsets (elements) ----
#define HXH   (0LL  * SZ_TOK)
#define HXL   (1LL  * SZ_TOK)
#define HX2   (2LL  * SZ_TOK)
#define HVX   (3LL  * SZ_TOK)
#define HQH   (4LL  * SZ_TOK)
#define HQL   (5LL  * SZ_TOK)
#define HQ2   (6LL  * SZ_TOK)
#define HKH   (7LL  * SZ_TOK)
#define HKL   (8LL  * SZ_TOK)
#define HVT   (9LL  * SZ_TOK)
#define HVQ   (10LL * SZ_TOK)
#define HVK   (11LL * SZ_TOK)
#define HVKK  (12LL * SZ_TOK)
#define HW0   (13LL * SZ_TOK)
#define WQMH  (HW0 + 0LL  * SZ_W)
#define WQML  (HW0 + 1LL  * SZ_W)
#define WQV   (HW0 + 2LL  * SZ_W)
#define WQP   (HW0 + 3LL  * SZ_W)
#define WKMH  (HW0 + 4LL  * SZ_W)
#define WKML  (HW0 + 5LL  * SZ_W)
#define WKV   (HW0 + 6LL  * SZ_W)
#define WKP   (HW0 + 7LL  * SZ_W)
#define WVMH  (HW0 + 8LL  * SZ_W)
#define WVML  (HW0 + 9LL  * SZ_W)
#define WVV   (HW0 + 10LL * SZ_W)
#define WVP   (HW0 + 11LL * SZ_W)
#define HPH   (HW0 + 12LL * SZ_W)
#define H_TOTAL (HPH + SZ_ATT)

// ---- bf16 pool offsets ----
#define BP2   (0LL)
#define BG    (1LL * SZ_ATT)
#define BVVT  (2LL * SZ_ATT)
#define BVVVT (2LL * SZ_ATT + SZ_TOK)
#define B_TOTAL (2LL * SZ_ATT + 2LL * SZ_TOK)

__device__ half  g_h[H_TOTAL];
__device__ bf16  g_b[B_TOTAL];
__device__ float g_kf[SZ_TOK];
__device__ float g_vf[SZ_TOK];

// ---------------------------------------------------------------------------
__device__ __forceinline__ uint32_t smem_to_u32(const void* p) {
    uint32_t a;
    asm("{ .reg .u64 t; cvta.to.shared.u64 t, %1; cvt.u32.u64 %0, t; }" : "=r"(a) : "l"(p));
    return a;
}
__device__ __forceinline__ void cp16(uint32_t s, const void* g) {
    asm volatile("cp.async.cg.shared.global [%0], [%1], 16;" :: "r"(s), "l"(g) : "memory");
}
#define CP_COMMIT() asm volatile("cp.async.commit_group;" ::: "memory")
#define CP_WAIT(n)  asm volatile("cp.async.wait_group %0;" :: "n"(n) : "memory")
#define SW128(x) ((x) ^ (((x) >> 3) & 0x70))
#define SW64(x)  ((x) ^ (((x) >> 3) & 0x30))

__device__ __forceinline__ void ldsm4(uint32_t* r, uint32_t addr) {
    asm volatile("ldmatrix.sync.aligned.m8n8.x4.shared.b16 {%0,%1,%2,%3}, [%4];"
        : "=r"(r[0]), "=r"(r[1]), "=r"(r[2]), "=r"(r[3]) : "r"(addr));
}
__device__ __forceinline__ void mma_h(float* c, const uint32_t* a, const uint32_t* b) {
    asm volatile(
        "mma.sync.aligned.m16n8k16.row.col.f32.f16.f16.f32 "
        "{%0,%1,%2,%3}, {%4,%5,%6,%7}, {%8,%9}, {%0,%1,%2,%3};"
        : "+f"(c[0]), "+f"(c[1]), "+f"(c[2]), "+f"(c[3])
        : "r"(a[0]), "r"(a[1]), "r"(a[2]), "r"(a[3]), "r"(b[0]), "r"(b[1]));
}
__device__ __forceinline__ void mma_b(float* c, const uint32_t* a, const uint32_t* b) {
    asm volatile(
        "mma.sync.aligned.m16n8k16.row.col.f32.bf16.bf16.f32 "
        "{%0,%1,%2,%3}, {%4,%5,%6,%7}, {%8,%9}, {%0,%1,%2,%3};"
        : "+f"(c[0]), "+f"(c[1]), "+f"(c[2]), "+f"(c[3])
        : "r"(a[0]), "r"(a[1]), "r"(a[2]), "r"(a[3]), "r"(b[0]), "r"(b[1]));
}
__device__ __forceinline__ void hsplit(float a, half* h, half* l) {
    half hh = __float2half(a);
    *h = hh; *l = __float2half(a - __half2float(hh));
}
__device__ __forceinline__ void st1(half* p, float v) { *p = __float2half(v); }
__device__ __forceinline__ void st1(bf16* p, float v) { *p = __float2bfloat16(v); }
__device__ __forceinline__ void stsp(half* h, half* l, float v) { hsplit(v, h, l); }
__device__ __forceinline__ void stsp(bf16* h, bf16* l, float v) {
    bf16 hh = __float2bfloat16(v);
    *h = hh; *l = __float2bfloat16(v - __bfloat162float(hh));
}
__device__ __forceinline__ uint32_t pkh(float a, float b) {
    return (uint32_t)__half_as_ushort(__float2half(a)) |
           ((uint32_t)__half_as_ushort(__float2half(b)) << 16);
}
__device__ __forceinline__ uint32_t pkb(float a, float b) {
    return (uint32_t)__bfloat16_as_ushort(__float2bfloat16(a)) |
           ((uint32_t)__bfloat16_as_ushort(__float2bfloat16(b)) << 16);
}
// packed splits for float4 -> (hi half2, lo half2)
__device__ __forceinline__ void hsplit2(float a, float b, uint32_t& hi, uint32_t& lo) {
    half ha = __float2half(a), hb = __float2half(b);
    hi = (uint32_t)__half_as_ushort(ha) | ((uint32_t)__half_as_ushort(hb) << 16);
    lo = pkh(a - __half2float(ha), b - __half2float(hb));
}

// ---------------------------------------------------------------------------
// R15 conv: float4 in, packed stores, 4 elements per thread
// ---------------------------------------------------------------------------
__global__ void conv_all_k(const float4* __restrict__ x4, const float4* __restrict__ vx4,
                           const float4* __restrict__ wqm4, const float4* __restrict__ wqv4,
                           const float4* __restrict__ wkm4, const float4* __restrict__ wkv4,
                           const float4* __restrict__ wvm4, const float4* __restrict__ wvv4,
                           half* __restrict__ hp) {
    const int i = blockIdx.x * 256 + threadIdx.x;   // float4 index
    const int e = i * 4;
    if (i < (int)(SZ_TOK / 4)) {
        float4 a = x4[i];
        float4 v = vx4[i];
        uint2 hi, lo;
        hsplit2(a.x, a.y, hi.x, lo.x);
        hsplit2(a.z, a.w, hi.y, lo.y);
        *(uint2*)(hp + HXH + e) = hi;
        *(uint2*)(hp + HXL + e) = lo;
        uint2 x2p;
        x2p.x = pkh(a.x * a.x, a.y * a.y);
        x2p.y = pkh(a.z * a.z, a.w * a.w);
        *(uint2*)(hp + HX2 + e) = x2p;
        uint2 vxp;
        vxp.x = pkh(v.x, v.y);
        vxp.y = pkh(v.z, v.w);
        *(uint2*)(hp + HVX + e) = vxp;
    }
    if (i < (int)(SZ_W / 4)) {
#define DO_W(M4, V4, OMH, OML, OV, OP) { \
        float4 m = (M4)[i]; float4 v = (V4)[i]; \
        uint2 hi, lo; \
        hsplit2(m.x, m.y, hi.x, lo.x); \
        hsplit2(m.z, m.w, hi.y, lo.y); \
        *(uint2*)(hp + (OMH) + e) = hi; \
        *(uint2*)(hp + (OML) + e) = lo; \
        uint2 vv; vv.x = pkh(v.x, v.y); vv.y = pkh(v.z, v.w); \
        *(uint2*)(hp + (OV) + e) = vv; \
        uint2 pp; \
        pp.x = pkh(fmaf(m.x, m.x, v.x), fmaf(m.y, m.y, v.y)); \
        pp.y = pkh(fmaf(m.z, m.z, v.z), fmaf(m.w, m.w, v.w)); \
        *(uint2*)(hp + (OP) + e) = pp; }
        DO_W(wqm4, wqv4, WQMH, WQML, WQV, WQP)
        DO_W(wkm4, wkv4, WKMH, WKML, WKV, WKP)
        DO_W(wvm4, wvv4, WVMH, WVML, WVV, WVP)
#undef DO_W
    }
}

// ---------------------------------------------------------------------------
// GEMM body: 64B SW64 rows, 3-stage pipeline, 1 sync/chunk (unchanged)
// ---------------------------------------------------------------------------
template<int BN, int MODE, bool F16, typename OT>
__device__ __forceinline__
void gemm_body(const uint16_t* __restrict__ A0, const uint16_t* __restrict__ A1,
               const uint16_t* __restrict__ B0, const uint16_t* __restrict__ B1,
               int K, int lda, int ldb, int ldc,
               long long sbA, long long shA, long long sbB, long long shB,
               long long sbC, long long shC, int bz,
               float alpha,
               float* __restrict__ cf, const float* __restrict__ addp,
               OT* __restrict__ ch, OT* __restrict__ cl, OT* __restrict__ cs,
               const float* __restrict__ auxf, OT* __restrict__ ds, int auxmode,
               int transC)
{
    constexpr int BM = 128, BK = 32;
    constexpr int NMATB = (MODE == 2) ? 1 : 2;
    constexpr int WARPS_N = (BN == 128) ? 4 : 2;
    constexpr int WARPS_M = 8 / WARPS_N;
    constexpr int WM = BM / WARPS_M, WN = BN / WARPS_N;
    constexpr int MT = WM / 16, NT = WN / 8;
    constexpr int ATILE = BM * 64;
    constexpr int BTILE = BN * 64;
    constexpr int BUFB  = 2 * ATILE + NMATB * BTILE;

    extern __shared__ char smem[];
    const uint32_t s32 = smem_to_u32(smem);
    const int tid = threadIdx.x;
    const int wid = tid >> 5, lane = tid & 31;
    const int wm = wid / WARPS_N, wn = wid % WARPS_N;

    const int bb = bz >> 4, hh = bz & 15;
    const long long offA = (long long)bb * sbA + (long long)hh * shA;
    const long long offB = (long long)bb * sbB + (long long)hh * shB;
    const long long offC = (long long)bb * sbC + (long long)hh * shC;
    const int m0 = blockIdx.y * BM;
    const int n0 = blockIdx.x * BN;

    auto loadbuf = [&](int kc, int buf) {
        const int k0 = kc * BK;
        const uint32_t b32 = s32 + buf * BUFB;
#pragma unroll
        for (int i = 0; i < BM * 4 / 256; i++) {
            const int c = tid + i * 256;
            const int row = c >> 2, seg = c & 3;
            const long long go = offA + (long long)(m0 + row) * lda + k0 + seg * 8;
            const uint32_t so = SW64((uint32_t)(row * 64 + seg * 16));
            cp16(b32 + so, A0 + go);
            cp16(b32 + ATILE + so, A1 + go);
        }
#pragma unroll
        for (int i = 0; i < BN * 4 / 256; i++) {
            const int c = tid + i * 256;
            const int row = c >> 2, seg = c & 3;
            const long long go = offB + (long long)(n0 + row) * ldb + k0 + seg * 8;
            const uint32_t so = SW64((uint32_t)(row * 64 + seg * 16));
            cp16(b32 + 2 * ATILE + so, B0 + go);
            if (NMATB == 2) cp16(b32 + 2 * ATILE + BTILE + so, B1 + go);
        }
        CP_COMMIT();
    };

    float acc[MT][NT][4];
#pragma unroll
    for (int i = 0; i < MT; i++)
#pragma unroll
        for (int j = 0; j < NT; j++)
#pragma unroll
            for (int r = 0; r < 4; r++) acc[i][j][r] = 0.f;

    const int NKC = K / BK;
    loadbuf(0, 0);
    if (NKC > 1) loadbuf(1, 1);

    for (int kc = 0; kc < NKC; kc++) {
        const int buf = kc % 3;
        if (kc < NKC - 1) { CP_WAIT(1); } else { CP_WAIT(0); }
        __syncthreads();
        if (kc + 2 < NKC) loadbuf(kc + 2, (kc + 2) % 3);

        const uint32_t b32 = s32 + buf * BUFB;
#pragma unroll
        for (int kh = 0; kh < 2; kh++) {
            const int kcol = kh * 16 + (lane >> 4) * 8;
            uint32_t afr[2][MT][4];
            uint32_t bfr[NMATB][NT][2];
#pragma unroll
            for (int mat = 0; mat < 2; mat++)
#pragma unroll
                for (int mt = 0; mt < MT; mt++) {
                    const int row = wm * WM + mt * 16 + (lane & 15);
                    ldsm4(afr[mat][mt], b32 + mat * ATILE + SW64((uint32_t)(row * 64 + kcol * 2)));
                }
#pragma unroll
            for (int mat = 0; mat < NMATB; mat++)
#pragma unroll
                for (int nt2 = 0; nt2 < NT / 2; nt2++) {
                    const int row = wn * WN + nt2 * 16 + (lane & 15);
                    uint32_t r[4];
                    ldsm4(r, b32 + 2 * ATILE + mat * BTILE + SW64((uint32_t)(row * 64 + kcol * 2)));
                    bfr[mat][2 * nt2][0]     = r[0]; bfr[mat][2 * nt2][1]     = r[2];
                    bfr[mat][2 * nt2 + 1][0] = r[1]; bfr[mat][2 * nt2 + 1][1] = r[3];
                }

#define DO_MMA(AM, BM_) \
            for (int mt = 0; mt < MT; mt++) \
                for (int nt = 0; nt < NT; nt++) { \
                    if (F16) mma_h(acc[mt][nt], afr[AM][mt], bfr[BM_][nt]); \
                    else     mma_b(acc[mt][nt], afr[AM][mt], bfr[BM_][nt]); \
                }
            DO_MMA(0, 0)
            if (MODE == 0) { DO_MMA(1, 0) DO_MMA(0, 1) }
            else if (MODE == 1) { DO_MMA(1, 1) }
            else { DO_MMA(1, 0) }
#undef DO_MMA
        }
    }

#pragma unroll
    for (int mt = 0; mt < MT; mt++) {
#pragma unroll
        for (int nt = 0; nt < NT; nt++) {
#pragma unroll
            for (int rp = 0; rp < 2; rp++) {
                const int m = m0 + wm * WM + mt * 16 + (lane >> 2) + rp * 8;
                const int nbase = n0 + wn * WN + nt * 8 + (lane & 3) * 2;
#pragma unroll
                for (int cc = 0; cc < 2; cc++) {
                    const int n = nbase + cc;
                    float val = alpha * acc[mt][nt][rp * 2 + cc];
                    const long long idx = offC + (long long)m * ldc + n;
                    if (addp) val += addp[idx];
                    if (cf) cf[idx] = val;
                    const long long bidx = transC
                        ? ((long long)(m >> 10) * ((long long)D_ * S_) + (long long)n * S_ + (m & (S_ - 1)))
                        : idx;
                    if (ch) stsp(ch + bidx, cl + bidx, val);
                    if (cs) st1(cs + bidx, val);
                    if (auxmode) {
                        const float t = (auxmode == 1) ? val * val
                                                       : fmaf(auxf[idx], auxf[idx], val);
                        st1(ds + bidx, t);
                    }
                }
            }
        }
    }
}

// ---------------------------------------------------------------------------
__global__ __launch_bounds__(256, 2)
void proj_a_k(half* __restrict__ hp, float* __restrict__ kf, float* __restrict__ vf) {
    const uint16_t* u = (const uint16_t*)hp;
    switch (blockIdx.z) {
    case 0:
        gemm_body<128, 0, true, half>(u + HXH, u + HXL, u + WQMH, u + WQML,
            D_, D_, D_, D_, 0, 0, 0, 0, 0, 0, 0, 1.f,
            nullptr, nullptr, hp + HQH, hp + HQL, nullptr, nullptr, hp + HQ2, 1, 0);
        break;
    case 1:
        gemm_body<128, 0, true, half>(u + HXH, u + HXL, u + WKMH, u + WKML,
            D_, D_, D_, D_, 0, 0, 0, 0, 0, 0, 0, 1.f,
            kf, nullptr, hp + HKH, hp + HKL, nullptr, nullptr, nullptr, 0, 0);
        break;
    case 2:
        gemm_body<128, 0, true, half>(u + HXH, u + HXL, u + WVMH, u + WVML,
            D_, D_, D_, D_, 0, 0, 0, 0, 0, 0, 0, 1.f,
            vf, nullptr, nullptr, nullptr, hp + HVT, nullptr, nullptr, 0, 1);
        break;
    default:
        gemm_body<128, 1, true, half>(u + HVX, u + HX2, u + WQP, u + WQV,
            D_, D_, D_, D_, 0, 0, 0, 0, 0, 0, 0, 1.f,
            nullptr, nullptr, nullptr, nullptr, hp + HVQ, nullptr, nullptr, 0, 0);
        break;
    }
}

__global__ __launch_bounds__(256, 2)
void proj_b_k(half* __restrict__ hp, bf16* __restrict__ bp,
              const float* __restrict__ kf, const float* __restrict__ vf) {
    const uint16_t* u = (const uint16_t*)hp;
    if (blockIdx.z == 0) {
        gemm_body<128, 1, true, half>(u + HVX, u + HX2, u + WKP, u + WKV,
            D_, D_, D_, D_, 0, 0, 0, 0, 0, 0, 0, 1.f,
            nullptr, nullptr, nullptr, nullptr, hp + HVK, kf, hp + HVKK, 2, 0);
    } else {
        gemm_body<128, 1, true, bf16>(u + HVX, u + HX2, u + WVP, u + WVV,
            D_, D_, D_, D_, 0, 0, 0, 0, 0, 0, 0, 1.f,
            nullptr, nullptr, nullptr, nullptr, bp + BVVT, vf, bp + BVVVT, 2, 1);
    }
}

// ---------------------------------------------------------------------------
// av body (R13). MODE 3: A0B0 only | MODE 1: A0B0+A1B1
// ---------------------------------------------------------------------------
template<int MODE, bool F16>
__device__ __forceinline__
void av_body(const uint16_t* __restrict__ A0, const uint16_t* __restrict__ A1,
             const uint16_t* __restrict__ B0f, const uint16_t* __restrict__ B1f,
             int bh, const float* __restrict__ addp, float* __restrict__ cf)
{
    constexpr int SK = 40;
    constexpr int BT = 64 * SK * 2;
    constexpr int NMATB = (MODE == 1) ? 2 : 1;
    constexpr int NMATA = (MODE == 3) ? 1 : 2;
    constexpr int BUFB = NMATB * BT;

    extern __shared__ char smem[];
    const uint32_t s32 = smem_to_u32(smem);
    const int tid = threadIdx.x, wid = tid >> 5, lane = tid & 31;
    const int wm = wid >> 1, wn = wid & 1;
    const int bb = bh >> 4, hh = bh & 15;
    const int m0 = blockIdx.y * 128;

    const long long attBase = (long long)bh << 20;
    const long long offB = (long long)bb * ((long long)D_ * S_) + (long long)hh * (DH_ * S_);
    const long long offC = (long long)bb * ((long long)S_ * D_) + (long long)hh * DH_;

    const int brow = tid >> 2, bseg = tid & 3;
    auto loadB = [&](int kc, int buf) {
        const int k0 = kc * 32;
        const uint32_t b32 = s32 + buf * BUFB;
        const long long go = offB + (long long)brow * S_ + k0 + bseg * 8;
        const uint32_t so = (uint32_t)(brow * SK + bseg * 8) * 2;
        cp16(b32 + so, B0f + go);
        if (NMATB == 2) cp16(b32 + BT + so, B1f + go);
        CP_COMMIT();
    };

    float acc[2][4][4];
#pragma unroll
    for (int mt = 0; mt < 2; mt++)
#pragma unroll
        for (int nt = 0; nt < 4; nt++)
#pragma unroll
            for (int r = 0; r < 4; r++) acc[mt][nt][r] = 0.f;

    const int mtile0 = (m0 >> 4) + wm * 2;

    loadB(0, 0);
    loadB(1, 1);
    for (int kc = 0; kc < 32; kc++) {
        const int buf = kc % 3;
        uint32_t af[NMATA][2][2][4];
#pragma unroll
        for (int mt = 0; mt < 2; mt++)
#pragma unroll
            for (int ks = 0; ks < 2; ks++) {
                const long long base = attBase + (long long)(mtile0 + mt) * 16384
                                     + (long long)(kc * 4 + ks * 2) * 128 + lane * 4;
                uint2 v0 = *(const uint2*)(A0 + base);
                uint2 v1 = *(const uint2*)(A0 + base + 128);
                af[0][mt][ks][0] = v0.x; af[0][mt][ks][1] = v0.y;
                af[0][mt][ks][2] = v1.x; af[0][mt][ks][3] = v1.y;
                if (NMATA == 2) {
                    uint2 w0 = *(const uint2*)(A1 + base);
                    uint2 w1 = *(const uint2*)(A1 + base + 128);
                    af[NMATA - 1][mt][ks][0] = w0.x; af[NMATA - 1][mt][ks][1] = w0.y;
                    af[NMATA - 1][mt][ks][2] = w1.x; af[NMATA - 1][mt][ks][3] = w1.y;
                }
            }

        if (kc < 30) { CP_WAIT(1); } else { CP_WAIT(0); }
        __syncthreads();
        if (kc + 2 < 32) loadB(kc + 2, (kc + 2) % 3);
        const uint32_t b32 = s32 + buf * BUFB;

#pragma unroll
        for (int ks = 0; ks < 2; ks++) {
            const int kcol = ks * 16 + (lane >> 4) * 8;
            uint32_t bfr[NMATB][4][2];
#pragma unroll
            for (int mat = 0; mat < NMATB; mat++)
#pragma unroll
                for (int nt2 = 0; nt2 < 2; nt2++) {
                    const int row = wn * 32 + nt2 * 16 + (lane & 15);
                    uint32_t r4[4];
                    ldsm4(r4, b32 + mat * BT + (uint32_t)(row * SK + kcol) * 2);
                    bfr[mat][2 * nt2][0]     = r4[0]; bfr[mat][2 * nt2][1]     = r4[2];
                    bfr[mat][2 * nt2 + 1][0] = r4[1]; bfr[mat][2 * nt2 + 1][1] = r4[3];
                }
#pragma unroll
            for (int mt = 0; mt < 2; mt++)
#pragma unroll
                for (int nt = 0; nt < 4; nt++) {
                    if (F16) {
                        mma_h(acc[mt][nt], af[0][mt][ks], bfr[0][nt]);
                        if (MODE != 3)
                            mma_h(acc[mt][nt], af[NMATA - 1][mt][ks], bfr[NMATB - 1][nt]);
                    } else {
                        mma_b(acc[mt][nt], af[0][mt][ks], bfr[0][nt]);
                        if (MODE != 3)
                            mma_b(acc[mt][nt], af[NMATA - 1][mt][ks], bfr[NMATB - 1][nt]);
                    }
                }
        }
    }

#pragma unroll
    for (int mt = 0; mt < 2; mt++)
#pragma unroll
        for (int nt = 0; nt < 4; nt++)
#pragma unroll
            for (int rp = 0; rp < 2; rp++) {
                const int m = m0 + wm * 32 + mt * 16 + (lane >> 2) + rp * 8;
                const int nbase = wn * 32 + nt * 8 + (lane & 3) * 2;
#pragma unroll
                for (int cc = 0; cc < 2; cc++) {
                    const int n = nbase + cc;
                    float val = acc[mt][nt][rp * 2 + cc];
                    const long long idx = offC + (long long)m * D_ + n;
                    if (addp) val += addp[idx];
                    cf[idx] = val;
                }
            }
}

__global__ __launch_bounds__(256, 2)
void av_k(half* __restrict__ hp, bf16* __restrict__ bp,
          const float* __restrict__ x, float* __restrict__ out) {
    const uint16_t* u = (const uint16_t*)hp;
    const int op = blockIdx.z >> 5;
    const int bh = blockIdx.z & 31;
    if (op == 0) {
        av_body<3, true>(u + HPH, nullptr, u + HVT, nullptr, bh, x, out);
    } else {
        av_body<1, false>((const uint16_t*)(bp + BG), (const uint16_t*)(bp + BP2),
                          (const uint16_t*)(bp + BVVVT), (const uint16_t*)(bp + BVVT),
                          bh, nullptr, out + SZ_TOK);
    }
}

// ---------------------------------------------------------------------------
// scores_k (exact R13 version): serial acc, p single fp16, packed frag stores
// ---------------------------------------------------------------------------
__global__ __launch_bounds__(256, 2)
void scores_k(const uint16_t* __restrict__ qh, const uint16_t* __restrict__ ql,
              const uint16_t* __restrict__ vq, const uint16_t* __restrict__ q2,
              const uint16_t* __restrict__ kh, const uint16_t* __restrict__ kl,
              const uint16_t* __restrict__ vkk, const uint16_t* __restrict__ vk,
              half* __restrict__ ph,
              bf16* __restrict__ p2, bf16* __restrict__ g)
{
    constexpr int QT = 16 * 128;
    constexpr int QB = 4 * QT;
    constexpr int KT = 64 * 128;
    constexpr int KBUF = 4 * KT;
    constexpr int RB = QB + 3 * KBUF;

    extern __shared__ char smem[];
    const uint32_t s32 = smem_to_u32(smem);
    const int tid = threadIdx.x, wid = tid >> 5, lane = tid & 31;
    const int bh = blockIdx.y, bb = bh >> 4, hh = bh & 15;
    const int m0 = blockIdx.x * 16;
    const long long tokOff = (long long)bb * S_ * D_ + (long long)hh * DH_;
    const long long fragBase = ((long long)bh << 20) + (long long)blockIdx.x * 16384;
    const float vscale = 1.0f / 1024.0f;

#pragma unroll
    for (int i = 0; i < 2; i++) {
        const int c = tid + i * 256;
        const int arr = c >> 7, r = (c >> 3) & 15, seg = c & 7;
        const uint16_t* src = (arr == 0) ? qh : (arr == 1) ? ql : (arr == 2) ? vq : q2;
        cp16(s32 + arr * QT + SW128((uint32_t)(r * 128 + seg * 16)),
             src + tokOff + (long long)(m0 + r) * D_ + seg * 8);
    }
    CP_COMMIT();

    auto loadK = [&](int c0, int buf) {
        const uint32_t kb = s32 + QB + buf * KBUF;
#pragma unroll
        for (int i = 0; i < 8; i++) {
            const int c = tid + i * 256;
            const int arr = c >> 9, rr = (c >> 3) & 63, seg = c & 7;
            const uint16_t* src = (arr == 0) ? kh : (arr == 1) ? kl : (arr == 2) ? vkk : vk;
            cp16(kb + arr * KT + SW128((uint32_t)(rr * 128 + seg * 16)),
                 src + tokOff + (long long)(c0 * 64 + rr) * D_ + seg * 8);
        }
        CP_COMMIT();
    };

    float acc[16][4];
#pragma unroll
    for (int c = 0; c < 16; c++)
#pragma unroll
        for (int r = 0; r < 4; r++) acc[c][r] = 0.f;

    const int brow = wid * 8 + (lane & 7);
    const int bgrp = (lane >> 3) * 8;

    loadK(0, 0);
    loadK(1, 1);
#pragma unroll
    for (int c0 = 0; c0 < 16; c0++) {
        const int buf = c0 % 3;
        if (c0 < 14) { CP_WAIT(1); } else { CP_WAIT(0); }
        __syncthreads();
        if (c0 + 2 < 16) loadK(c0 + 2, (c0 + 2) % 3);
        const uint32_t kb = s32 + QB + buf * KBUF;

        float accVS[4] = {0.f, 0.f, 0.f, 0.f};
#pragma unroll
        for (int kp = 0; kp < 2; kp++) {
            uint32_t bfp[4][4];
#pragma unroll
            for (int m = 0; m < 4; m++)
                ldsm4(bfp[m], kb + m * KT + SW128((uint32_t)(brow * 128 + (kp * 32 + bgrp) * 2)));
#pragma unroll
            for (int kk = 0; kk < 2; kk++) {
                const int ks = kp * 2 + kk;
                const int kcolA = ks * 16 + (lane >> 4) * 8;
                uint32_t af[4][4];
#pragma unroll
                for (int m = 0; m < 4; m++)
                    ldsm4(af[m], s32 + m * QT + SW128((uint32_t)((lane & 15) * 128 + kcolA * 2)));
                const uint32_t* b0 = &bfp[0][kk * 2];
                const uint32_t* b1 = &bfp[1][kk * 2];
                const uint32_t* b2 = &bfp[2][kk * 2];
                const uint32_t* b3 = &bfp[3][kk * 2];
                mma_h(acc[c0], af[0], b0);
                mma_h(acc[c0], af[1], b0);
                mma_h(acc[c0], af[0], b1);
                mma_h(accVS,   af[2], b2);
                mma_h(accVS,   af[3], b3);
            }
        }
        {
            const long long fidx = fragBase + (long long)(c0 * 8 + wid) * 128 + lane * 4;
            uint2 v;
            v.x = pkb(accVS[0] * vscale, accVS[1] * vscale);
            v.y = pkb(accVS[2] * vscale, accVS[3] * vscale);
            *(uint2*)(g + fidx) = v;
        }
    }

    float* red = (float*)(smem + RB);
    const int r0 = lane >> 2;
    const float sscale = 1.0f / 32.0f;
    float mx[2] = {-1e30f, -1e30f};
#pragma unroll
    for (int c = 0; c < 16; c++)
#pragma unroll
        for (int rp = 0; rp < 2; rp++)
            mx[rp] = fmaxf(mx[rp], fmaxf(acc[c][rp * 2], acc[c][rp * 2 + 1]));
    mx[0] *= sscale; mx[1] *= sscale;
#pragma unroll
    for (int d = 1; d <= 2; d <<= 1) {
        mx[0] = fmaxf(mx[0], __shfl_xor_sync(0xffffffff, mx[0], d));
        mx[1] = fmaxf(mx[1], __shfl_xor_sync(0xffffffff, mx[1], d));
    }
    __syncthreads();
    if ((lane & 3) == 0) {
        red[r0 * 8 + wid] = mx[0];
        red[(r0 + 8) * 8 + wid] = mx[1];
    }
    __syncthreads();
    float rmx[2];
#pragma unroll
    for (int rp = 0; rp < 2; rp++) {
        float v = -1e30f;
#pragma unroll
        for (int w = 0; w < 8; w++) v = fmaxf(v, red[(r0 + rp * 8) * 8 + w]);
        rmx[rp] = v;
    }
    __syncthreads();
    float sm[2] = {0.f, 0.f};
#pragma unroll
    for (int c = 0; c < 16; c++)
#pragma unroll
        for (int rp = 0; rp < 2; rp++)
#pragma unroll
            for (int cc = 0; cc < 2; cc++) {
                float e = __expf(acc[c][rp * 2 + cc] * sscale - rmx[rp]);
                acc[c][rp * 2 + cc] = e;
                sm[rp] += e;
            }
#pragma unroll
    for (int d = 1; d <= 2; d <<= 1) {
        sm[0] += __shfl_xor_sync(0xffffffff, sm[0], d);
        sm[1] += __shfl_xor_sync(0xffffffff, sm[1], d);
    }
    if ((lane & 3) == 0) {
        red[r0 * 8 + wid] = sm[0];
        red[(r0 + 8) * 8 + wid] = sm[1];
    }
    __syncthreads();
    float inv[2];
#pragma unroll
    for (int rp = 0; rp < 2; rp++) {
        float v = 0.f;
#pragma unroll
        for (int w = 0; w < 8; w++) v += red[(r0 + rp * 8) * 8 + w];
        inv[rp] = 1.0f / v;
    }

#pragma unroll
    for (int c = 0; c < 16; c++) {
        const long long fidx = fragBase + (long long)(c * 8 + wid) * 128 + lane * 4;
        const float p0 = acc[c][0] * inv[0];
        const float p1 = acc[c][1] * inv[0];
        const float p2v = acc[c][2] * inv[1];
        const float p3 = acc[c][3] * inv[1];
        uint2 vph;
        vph.x = pkh(p0, p1);
        vph.y = pkh(p2v, p3);
        *(uint2*)(ph + fidx) = vph;
        uint2 vp2;
        vp2.x = pkb(p0 * p0, p1 * p1);
        vp2.y = pkb(p2v * p2v, p3 * p3);
        *(uint2*)(p2 + fidx) = vp2;
        const uint2 vsp = *(const uint2*)(g + fidx);
        const float vs0 = __bfloat162float(__ushort_as_bfloat16((unsigned short)(vsp.x & 0xffff)));
        const float vs1 = __bfloat162float(__ushort_as_bfloat16((unsigned short)(vsp.x >> 16)));
        const float vs2 = __bfloat162float(__ushort_as_bfloat16((unsigned short)(vsp.y & 0xffff)));
        const float vs3 = __bfloat162float(__ushort_as_bfloat16((unsigned short)(vsp.y >> 16)));
        const float pm0 = p0 * (1.0f - p0), pm1 = p1 * (1.0f - p1);
        const float pm2 = p2v * (1.0f - p2v), pm3 = p3 * (1.0f - p3);
        uint2 vg;
        vg.x = pkb(pm0 * pm0 * vs0, pm1 * pm1 * vs1);
        vg.y = pkb(pm2 * pm2 * vs2, pm3 * pm3 * vs3);
        *(uint2*)(g + fidx) = vg;
    }
}

// ---------------------------------------------------------------------------
extern "C" void kernel_launch(void* const* d_in, const int* in_sizes, int n_in,
                              void* d_out, int out_size)
{
    (void)in_sizes; (void)n_in; (void)out_size;
    const float* x      = (const float*)d_in[0];
    const float* var_x  = (const float*)d_in[1];
    const float* wq_mu  = (const float*)d_in[2];
    const float* wq_var = (const float*)d_in[3];
    const float* wk_mu  = (const float*)d_in[4];
    const float* wk_var = (const float*)d_in[5];
    const float* wv_mu  = (const float*)d_in[6];
    const float* wv_var = (const float*)d_in[7];
    float* out = (float*)d_out;

    half* hp = nullptr;  cudaGetSymbolAddress((void**)&hp, g_h);
    bf16* bp = nullptr;  cudaGetSymbolAddress((void**)&bp, g_b);
    float* kf = nullptr; cudaGetSymbolAddress((void**)&kf, g_kf);
    float* vf = nullptr; cudaGetSymbolAddress((void**)&vf, g_vf);

    const int SM128 = 3 * 32768;
    const int SMAV  = 3 * 10240;
    const int SMSC  = 8192 + 3 * 32768 + 512;
    cudaFuncSetAttribute(proj_a_k, cudaFuncAttributeMaxDynamicSharedMemorySize, SM128);
    cudaFuncSetAttribute(proj_b_k, cudaFuncAttributeMaxDynamicSharedMemorySize, SM128);
    cudaFuncSetAttribute(av_k,     cudaFuncAttributeMaxDynamicSharedMemorySize, SMAV);
    cudaFuncSetAttribute(scores_k, cudaFuncAttributeMaxDynamicSharedMemorySize, SMSC);

    conv_all_k<<<(int)(SZ_TOK / 4 / 256), 256>>>(
        (const float4*)x, (const float4*)var_x,
        (const float4*)wq_mu, (const float4*)wq_var,
        (const float4*)wk_mu, (const float4*)wk_var,
        (const float4*)wv_mu, (const float4*)wv_var, hp);

    proj_a_k<<<dim3(8, 16, 4), 256, SM128>>>(hp, kf, vf);
    proj_b_k<<<dim3(8, 16, 2), 256, SM128>>>(hp, bp, kf, vf);

    const uint16_t* u = (const uint16_t*)hp;
    scores_k<<<dim3(64, 32), 256, SMSC>>>(
        u + HQH, u + HQL, u + HVQ, u + HQ2,
        u + HKH, u + HKL, u + HVKK, u + HVK,
        hp + HPH, bp + BP2, bp + BG);

    av_k<<<dim3(1, 8, 64), 256, SMAV>>>(hp, bp, x, out);
}